// round 2
// baseline (speedup 1.0000x reference)
#include <cuda_runtime.h>
#include <cuda_bf16.h>
#include <math.h>

// Problem constants
#define BATCH 8
#define LEN   2048
#define DIM   1024
#define DFF   4096
#define NFFT  4096
#define LN_EPS 1e-5f

// ---------------------------------------------------------------------------
// Static device scratch (no allocation allowed)
// ---------------------------------------------------------------------------
__device__ float  g_lnz  [BATCH * LEN * DIM];        // 64 MB : LN(z)
__device__ float  g_hfilt[LEN * DIM];                // 8  MB : ffn(pos)
__device__ float2 g_wfh  [DIM * NFFT];               // 32 MB : filter spectrum
__device__ float  g_znew [BATCH * LEN * DIM];        // 64 MB
__device__ float  g_X    [BATCH * LEN * DIM];        // 64 MB : LN(znew)
__device__ float  g_H    [BATCH * LEN * DFF];        // 256MB : FFN hidden (reused)

// ---------------------------------------------------------------------------
// FFT helpers: 4096-point complex FFT in shared memory, 256 threads/block
// ---------------------------------------------------------------------------
__device__ __forceinline__ float2 cmul(float2 a, float2 b) {
    return make_float2(a.x * b.x - a.y * b.y, a.x * b.y + a.y * b.x);
}

// SIGN = -1 : forward ; SIGN = +1 : inverse (unscaled)
template <int SIGN>
__device__ void fft4096(float2* sm, const float2* tw) {
    const int tid = threadIdx.x;  // 256 threads
    __syncthreads();
    // bit-reversal permutation (12 bits)
    for (int i = tid; i < NFFT; i += 256) {
        int r = __brev(i) >> 20;
        if (r > i) { float2 t = sm[i]; sm[i] = sm[r]; sm[r] = t; }
    }
    __syncthreads();
    for (int len = 2; len <= NFFT; len <<= 1) {
        const int half = len >> 1;
        const int step = NFFT / len;
        for (int j = tid; j < NFFT / 2; j += 256) {
            const int pos = j & (half - 1);
            const int i0  = 2 * j - pos;
            const int i1  = i0 + half;
            float2 w = tw[pos * step];
            if (SIGN > 0) w.y = -w.y;
            float2 u = sm[i0];
            float2 v = cmul(sm[i1], w);
            sm[i0] = make_float2(u.x + v.x, u.y + v.y);
            sm[i1] = make_float2(u.x - v.x, u.y - v.y);
        }
        __syncthreads();
    }
}

__device__ __forceinline__ void fill_twiddles(float2* tw) {
    for (int k = threadIdx.x; k < NFFT / 2; k += 256) {
        float s, c;
        sincosf(-6.2831853071795864769f * (float)k / (float)NFFT, &s, &c);
        tw[k] = make_float2(c, s);
    }
}

// ---------------------------------------------------------------------------
// LayerNorm over last axis (D=1024). One block per row, 256 threads.
// ---------------------------------------------------------------------------
__global__ void layernorm_rows(const float* __restrict__ x,
                               const float* __restrict__ gvec,
                               const float* __restrict__ bvec,
                               float* __restrict__ y) {
    const int row = blockIdx.x;
    const int tid = threadIdx.x;
    const float4* xr = reinterpret_cast<const float4*>(x + (size_t)row * DIM);
    float4 v = xr[tid];
    float s  = v.x + v.y + v.z + v.w;
    float s2 = v.x * v.x + v.y * v.y + v.z * v.z + v.w * v.w;
    __shared__ float rs[256], rs2[256];
    rs[tid] = s; rs2[tid] = s2;
    __syncthreads();
    for (int o = 128; o > 0; o >>= 1) {
        if (tid < o) { rs[tid] += rs[tid + o]; rs2[tid] += rs2[tid + o]; }
        __syncthreads();
    }
    const float mean = rs[0] * (1.0f / DIM);
    const float var  = rs2[0] * (1.0f / DIM) - mean * mean;
    const float rstd = rsqrtf(var + LN_EPS);
    const float4 gg = reinterpret_cast<const float4*>(gvec)[tid];
    const float4 bb = reinterpret_cast<const float4*>(bvec)[tid];
    float4 o;
    o.x = (v.x - mean) * rstd * gg.x + bb.x;
    o.y = (v.y - mean) * rstd * gg.y + bb.y;
    o.z = (v.z - mean) * rstd * gg.z + bb.z;
    o.w = (v.w - mean) * rstd * gg.w + bb.w;
    reinterpret_cast<float4*>(y + (size_t)row * DIM)[tid] = o;
}

// ---------------------------------------------------------------------------
// Filter spectrum: per channel d, FFT( window(t) * hfilt[t,d], padded to 4096 )
// ---------------------------------------------------------------------------
__global__ void filter_fft(const float* __restrict__ hfilt,
                           const float* __restrict__ a,
                           float2* __restrict__ wfh) {
    __shared__ float2 data[NFFT];
    __shared__ float2 tw[NFFT / 2];
    const int d   = blockIdx.x;
    const int tid = threadIdx.x;
    const float ea = expf(a[0]);
    for (int t = tid; t < LEN; t += 256) {
        float w = expf(-(float)t * ea);
        data[t] = make_float2(hfilt[(size_t)t * DIM + d] * w, 0.0f);
    }
    for (int t = LEN + tid; t < NFFT; t += 256) data[t] = make_float2(0.0f, 0.0f);
    fill_twiddles(tw);
    fft4096<-1>(data, tw);
    for (int k = tid; k < NFFT; k += 256) wfh[(size_t)d * NFFT + k] = data[k];
}

// ---------------------------------------------------------------------------
// FFT convolution per (batch, dim) column:
//   znew[b,t,d] = IFFT( FFT(lnz[b,:,d] pad) * WFH[d] )[t].re / N + hidden[t,d]
// ---------------------------------------------------------------------------
__global__ void fftconv(const float* __restrict__ lnz,
                        const float2* __restrict__ wfh,
                        const float* __restrict__ hidden,
                        float* __restrict__ znew) {
    __shared__ float2 data[NFFT];
    __shared__ float2 tw[NFFT / 2];
    const int col = blockIdx.x;            // b * DIM + d
    const int b   = col >> 10;
    const int d   = col & (DIM - 1);
    const int tid = threadIdx.x;
    for (int t = tid; t < LEN; t += 256)
        data[t] = make_float2(lnz[((size_t)b * LEN + t) * DIM + d], 0.0f);
    for (int t = LEN + tid; t < NFFT; t += 256) data[t] = make_float2(0.0f, 0.0f);
    fill_twiddles(tw);
    fft4096<-1>(data, tw);
    for (int k = tid; k < NFFT; k += 256)
        data[k] = cmul(data[k], wfh[(size_t)d * NFFT + k]);
    fft4096<1>(data, tw);
    const float inv = 1.0f / (float)NFFT;
    for (int t = tid; t < LEN; t += 256)
        znew[((size_t)b * LEN + t) * DIM + d] =
            data[t].x * inv + hidden[(size_t)t * DIM + d];
}

// ---------------------------------------------------------------------------
// Tiled SGEMM: C[M,N] = act(A[M,K] @ W[K,N] + bias) (+ add)
// BM=BN=128, BK=16, 256 threads, 8x8 per thread. M,N,K divisible by tiles.
// ACT: 0 = none, 1 = silu
// ---------------------------------------------------------------------------
template <int ACT, bool HAS_ADD>
__global__ __launch_bounds__(256)
void sgemm(const float* __restrict__ A, const float* __restrict__ W,
           const float* __restrict__ bias, const float* __restrict__ add,
           float* __restrict__ C, int M, int N, int K) {
    __shared__ float As[16][128];
    __shared__ float Bs[16][128];
    const int tid = threadIdx.x;
    const int tx = tid & 15;     // 0..15  -> N micro tile
    const int ty = tid >> 4;     // 0..15  -> M micro tile
    const int bm = blockIdx.y * 128;
    const int bn = blockIdx.x * 128;

    float acc[8][8];
#pragma unroll
    for (int i = 0; i < 8; i++)
#pragma unroll
        for (int j = 0; j < 8; j++) acc[i][j] = 0.0f;

    for (int k0 = 0; k0 < K; k0 += 16) {
        // load A tile (transposed into As[k][m])
#pragma unroll
        for (int s = 0; s < 2; s++) {
            int idx = tid + s * 256;          // 0..511
            int r   = idx >> 2;               // 0..127
            int c4  = idx & 3;                // 0..3
            float4 v = *reinterpret_cast<const float4*>(
                &A[(size_t)(bm + r) * K + k0 + c4 * 4]);
            As[c4 * 4 + 0][r] = v.x;
            As[c4 * 4 + 1][r] = v.y;
            As[c4 * 4 + 2][r] = v.z;
            As[c4 * 4 + 3][r] = v.w;
        }
        // load B tile
#pragma unroll
        for (int s = 0; s < 2; s++) {
            int idx = tid + s * 256;
            int r   = idx >> 5;               // 0..15
            int c4  = idx & 31;               // 0..31
            *reinterpret_cast<float4*>(&Bs[r][c4 * 4]) =
                *reinterpret_cast<const float4*>(
                    &W[(size_t)(k0 + r) * N + bn + c4 * 4]);
        }
        __syncthreads();
#pragma unroll
        for (int kk = 0; kk < 16; kk++) {
            float ra[8], rb[8];
            *reinterpret_cast<float4*>(ra)     = *reinterpret_cast<float4*>(&As[kk][ty * 8]);
            *reinterpret_cast<float4*>(ra + 4) = *reinterpret_cast<float4*>(&As[kk][ty * 8 + 4]);
            *reinterpret_cast<float4*>(rb)     = *reinterpret_cast<float4*>(&Bs[kk][tx * 8]);
            *reinterpret_cast<float4*>(rb + 4) = *reinterpret_cast<float4*>(&Bs[kk][tx * 8 + 4]);
#pragma unroll
            for (int i = 0; i < 8; i++)
#pragma unroll
                for (int j = 0; j < 8; j++) acc[i][j] += ra[i] * rb[j];
        }
        __syncthreads();
    }

    // epilogue
#pragma unroll
    for (int i = 0; i < 8; i++) {
        const int r = bm + ty * 8 + i;
#pragma unroll
        for (int j = 0; j < 8; j++) {
            const int c = bn + tx * 8 + j;
            float v = acc[i][j] + bias[c];
            if (ACT == 1) v = v / (1.0f + expf(-v));   // silu
            if (HAS_ADD) v += add[(size_t)r * N + c];
            C[(size_t)r * N + c] = v;
        }
    }
}

// ---------------------------------------------------------------------------
// Launch
// ---------------------------------------------------------------------------
extern "C" void kernel_launch(void* const* d_in, const int* in_sizes, int n_in,
                              void* d_out, int out_size) {
    const float* z      = (const float*)d_in[0];
    const float* pos    = (const float*)d_in[1];
    const float* a      = (const float*)d_in[2];
    const float* hidden = (const float*)d_in[3];
    const float* ln_g   = (const float*)d_in[4];
    const float* ln_b   = (const float*)d_in[5];
    const float* wp1    = (const float*)d_in[6];
    const float* bp1    = (const float*)d_in[7];
    const float* wp2    = (const float*)d_in[8];
    const float* bp2    = (const float*)d_in[9];
    const float* w1     = (const float*)d_in[10];
    const float* b1     = (const float*)d_in[11];
    const float* w2     = (const float*)d_in[12];
    const float* b2     = (const float*)d_in[13];
    float* out = (float*)d_out;

    float *lnz, *hfilt, *znew, *X, *H;
    float2* wfh;
    cudaGetSymbolAddress((void**)&lnz,   g_lnz);
    cudaGetSymbolAddress((void**)&hfilt, g_hfilt);
    cudaGetSymbolAddress((void**)&wfh,   g_wfh);
    cudaGetSymbolAddress((void**)&znew,  g_znew);
    cudaGetSymbolAddress((void**)&X,     g_X);
    cudaGetSymbolAddress((void**)&H,     g_H);

    // 1) filter FFN on positional encodings: h = ffn(pos)
    sgemm<1, false><<<dim3(DFF / 128, LEN / 128), 256>>>(
        pos, wp1, bp1, nullptr, H, LEN, DFF, DIM);
    sgemm<0, false><<<dim3(DIM / 128, LEN / 128), 256>>>(
        H, wp2, bp2, nullptr, hfilt, LEN, DIM, DFF);

    // 2) filter spectrum: WFH[d] = FFT(window * h[:,d], 4096)
    filter_fft<<<DIM, 256>>>(hfilt, a, wfh);

    // 3) LN(z)
    layernorm_rows<<<BATCH * LEN, 256>>>(z, ln_g, ln_b, lnz);

    // 4) FFT convolution per (b, d) column + hidden residual
    fftconv<<<BATCH * DIM, 256>>>(lnz, wfh, hidden, znew);

    // 5) LN(znew)
    layernorm_rows<<<BATCH * LEN, 256>>>(znew, ln_g, ln_b, X);

    // 6) main FFN + residual: out = ffn(X) + znew
    sgemm<1, false><<<dim3(DFF / 128, (BATCH * LEN) / 128), 256>>>(
        X, w1, b1, nullptr, H, BATCH * LEN, DFF, DIM);
    sgemm<0, true><<<dim3(DIM / 128, (BATCH * LEN) / 128), 256>>>(
        H, w2, b2, znew, out, BATCH * LEN, DIM, DFF);
}

// round 4
// speedup vs baseline: 1.9525x; 1.9525x over previous
#include <cuda_runtime.h>
#include <cuda_bf16.h>
#include <math.h>
#include <cstdint>

// Problem constants
#define BATCH 8
#define LEN   2048
#define DIM   1024
#define DFF   4096
#define NFFT  4096
#define LN_EPS 1e-5f

// ---------------------------------------------------------------------------
// Static device scratch (no allocation allowed)
// ---------------------------------------------------------------------------
__device__ float  g_lnz  [BATCH * LEN * DIM];        // LN(z)  (fp32, for fftconv)
__device__ float  g_hfilt[LEN * DIM];                // ffn(pos) fp32
__device__ float2 g_wfh  [DIM * NFFT];               // filter spectrum
__device__ float  g_znew [BATCH * LEN * DIM];        // conv out + hidden
__device__ __nv_bfloat16 g_Xh[BATCH * LEN * DIM];    // LN(znew) split hi
__device__ __nv_bfloat16 g_Xl[BATCH * LEN * DIM];    // LN(znew) split lo
__device__ __nv_bfloat16 g_Hh[BATCH * LEN * DFF];    // FFN hidden split hi
__device__ __nv_bfloat16 g_Hl[BATCH * LEN * DFF];    // FFN hidden split lo
__device__ __nv_bfloat16 g_posh[LEN * DIM];
__device__ __nv_bfloat16 g_posl[LEN * DIM];
// transposed + split weights: [N, K] layout
__device__ __nv_bfloat16 g_wp1t_h[DFF * DIM];
__device__ __nv_bfloat16 g_wp1t_l[DFF * DIM];
__device__ __nv_bfloat16 g_wp2t_h[DIM * DFF];
__device__ __nv_bfloat16 g_wp2t_l[DIM * DFF];
__device__ __nv_bfloat16 g_w1t_h[DFF * DIM];
__device__ __nv_bfloat16 g_w1t_l[DFF * DIM];
__device__ __nv_bfloat16 g_w2t_h[DIM * DFF];
__device__ __nv_bfloat16 g_w2t_l[DIM * DFF];

// ---------------------------------------------------------------------------
// PTX wrappers (baseline sm_80+ instructions only — NO sm_103a features)
// ---------------------------------------------------------------------------
__device__ __forceinline__ uint32_t smem_u32(const void* p) {
    uint32_t a;
    asm("{ .reg .u64 t; cvta.to.shared.u64 t, %1; cvt.u32.u64 %0, t; }"
        : "=r"(a) : "l"(p));
    return a;
}

__device__ __forceinline__ void cpasync16(uint32_t s, const void* g) {
    asm volatile("cp.async.cg.shared.global [%0], [%1], 16;"
                 :: "r"(s), "l"(g) : "memory");
}
__device__ __forceinline__ void cp_commit() {
    asm volatile("cp.async.commit_group;" ::: "memory");
}
template <int N>
__device__ __forceinline__ void cp_wait() {
    asm volatile("cp.async.wait_group %0;" :: "n"(N) : "memory");
}

__device__ __forceinline__ void ldm_x4(uint32_t& r0, uint32_t& r1,
                                       uint32_t& r2, uint32_t& r3, uint32_t a) {
    asm volatile("ldmatrix.sync.aligned.m8n8.x4.shared.b16 {%0,%1,%2,%3}, [%4];"
                 : "=r"(r0), "=r"(r1), "=r"(r2), "=r"(r3) : "r"(a));
}
__device__ __forceinline__ void ldm_x2(uint32_t& r0, uint32_t& r1, uint32_t a) {
    asm volatile("ldmatrix.sync.aligned.m8n8.x2.shared.b16 {%0,%1}, [%2];"
                 : "=r"(r0), "=r"(r1) : "r"(a));
}

__device__ __forceinline__ void mma_bf16(float4& d, const uint32_t* a,
                                         uint32_t b0, uint32_t b1) {
    asm volatile(
        "mma.sync.aligned.m16n8k16.row.col.f32.bf16.bf16.f32 "
        "{%0,%1,%2,%3}, {%4,%5,%6,%7}, {%8,%9}, {%0,%1,%2,%3};"
        : "+f"(d.x), "+f"(d.y), "+f"(d.z), "+f"(d.w)
        : "r"(a[0]), "r"(a[1]), "r"(a[2]), "r"(a[3]), "r"(b0), "r"(b1));
}

// ---------------------------------------------------------------------------
// HMMA GEMM: C[M,N] = epi( (Ah+Al)[M,K] @ (Bh+Bl)[N,K]^T + bias )
// split-bf16 3-term product: Ah*Bh + Ah*Bl + Al*Bh
// BM=BN=128, BK=32, 256 threads (8 warps as 4m x 2n, warp tile 32x64),
// cp.async double-buffered smem, padded rows (80B stride) for ldmatrix.
// ACT: 0 none, 1 silu.  SPLIT_OUT: write Ch/Cl bf16.  HAS_ADD: += add.
// ---------------------------------------------------------------------------
#define GBM 128
#define GBN 128
#define GBK 32
#define TPAD 40                      // padded row stride in bf16 elems (80B)
#define TILE_B (128 * TPAD * 2)      // 10240 bytes per matrix tile
#define STAGE_B (4 * TILE_B)         // Ah, Al, Bh, Bl
#define GEMM_SMEM (2 * STAGE_B)      // double buffer: 81920 bytes

template <int ACT, bool SPLIT_OUT, bool HAS_ADD>
__global__ __launch_bounds__(256)
void gemm_mma(const __nv_bfloat16* __restrict__ Ah, const __nv_bfloat16* __restrict__ Al,
              const __nv_bfloat16* __restrict__ Bh, const __nv_bfloat16* __restrict__ Bl,
              const float* __restrict__ bias, const float* __restrict__ add,
              float* __restrict__ Cf, __nv_bfloat16* __restrict__ Ch,
              __nv_bfloat16* __restrict__ Cl, int M, int N, int K) {
    extern __shared__ char smem[];
    const uint32_t sbase = smem_u32(smem);
    const int tid  = threadIdx.x;
    const int lane = tid & 31;
    const int wid  = tid >> 5;
    const int wm   = wid & 3;        // 4 warp rows  (32 M each)
    const int wn   = wid >> 2;       // 2 warp cols  (64 N each)
    const int bm = blockIdx.y * GBM;
    const int bn = blockIdx.x * GBN;

    // per-thread gmem load coords: 2 chunks of 16B per matrix per k-tile
    const int r0 = tid >> 2;               // rows 0..63
    const int c0 = tid & 3;                // 16B chunk 0..3
    const uint32_t so0 = (uint32_t)(r0 * 80 + c0 * 16);
    const uint32_t so1 = (uint32_t)((r0 + 64) * 80 + c0 * 16);

    auto issue_loads = [&](int stage, int k0) {
        const uint32_t sb = sbase + stage * STAGE_B;
        const size_t ga0 = (size_t)(bm + r0) * K + k0 + c0 * 8;
        const size_t ga1 = (size_t)(bm + r0 + 64) * K + k0 + c0 * 8;
        const size_t gb0 = (size_t)(bn + r0) * K + k0 + c0 * 8;
        const size_t gb1 = (size_t)(bn + r0 + 64) * K + k0 + c0 * 8;
        cpasync16(sb + so0,              Ah + ga0);
        cpasync16(sb + so1,              Ah + ga1);
        cpasync16(sb + TILE_B + so0,     Al + ga0);
        cpasync16(sb + TILE_B + so1,     Al + ga1);
        cpasync16(sb + 2 * TILE_B + so0, Bh + gb0);
        cpasync16(sb + 2 * TILE_B + so1, Bh + gb1);
        cpasync16(sb + 3 * TILE_B + so0, Bl + gb0);
        cpasync16(sb + 3 * TILE_B + so1, Bl + gb1);
        cp_commit();
    };

    float4 acc[2][8];
#pragma unroll
    for (int i = 0; i < 2; i++)
#pragma unroll
        for (int j = 0; j < 8; j++) acc[i][j] = make_float4(0.f, 0.f, 0.f, 0.f);

    // ldmatrix lane addressing (byte offsets within a tile)
    const int a_row = (lane & 7) + ((lane >> 3) & 1) * 8;   // row within 16
    const int a_kc  = ((lane >> 4) & 1) * 8;                // k col 0 or 8
    const int b_row = lane & 7;
    const int b_kc  = ((lane >> 3) & 1) * 8;                // lanes 0-15 used

    const int NT = K / GBK;
    issue_loads(0, 0);

    for (int kt = 0; kt < NT; kt++) {
        if (kt + 1 < NT) issue_loads((kt + 1) & 1, (kt + 1) * GBK);
        if (kt + 1 < NT) cp_wait<1>(); else cp_wait<0>();
        __syncthreads();

        const uint32_t st = sbase + (kt & 1) * STAGE_B;
        const uint32_t As_h = st;
        const uint32_t As_l = st + TILE_B;
        const uint32_t Bs_h = st + 2 * TILE_B;
        const uint32_t Bs_l = st + 3 * TILE_B;

#pragma unroll
        for (int k16 = 0; k16 < 2; k16++) {
            uint32_t ah[2][4], al[2][4];
#pragma unroll
            for (int i = 0; i < 2; i++) {
                const uint32_t ao =
                    (uint32_t)((wm * 32 + i * 16 + a_row) * 80 +
                               (k16 * 16 + a_kc) * 2);
                ldm_x4(ah[i][0], ah[i][1], ah[i][2], ah[i][3], As_h + ao);
                ldm_x4(al[i][0], al[i][1], al[i][2], al[i][3], As_l + ao);
            }
#pragma unroll
            for (int j = 0; j < 8; j++) {
                const uint32_t bo =
                    (uint32_t)((wn * 64 + j * 8 + b_row) * 80 +
                               (k16 * 16 + b_kc) * 2);
                uint32_t bh0, bh1, bl0, bl1;
                ldm_x2(bh0, bh1, Bs_h + bo);
                ldm_x2(bl0, bl1, Bs_l + bo);
#pragma unroll
                for (int i = 0; i < 2; i++) {
                    mma_bf16(acc[i][j], ah[i], bh0, bh1);
                    mma_bf16(acc[i][j], ah[i], bl0, bl1);
                    mma_bf16(acc[i][j], al[i], bh0, bh1);
                }
            }
        }
        __syncthreads();
    }

    // epilogue: thread (lane) holds rows qr, qr+8 and col pair qc per (i,j)
    const int qr = lane >> 2;
    const int qc = (lane & 3) * 2;
#pragma unroll
    for (int i = 0; i < 2; i++) {
#pragma unroll
        for (int j = 0; j < 8; j++) {
            const int gr0 = bm + wm * 32 + i * 16 + qr;
            const int gc  = bn + wn * 64 + j * 8 + qc;
            const float b0 = bias[gc];
            const float b1 = bias[gc + 1];
            float v00 = acc[i][j].x + b0, v01 = acc[i][j].y + b1;
            float v10 = acc[i][j].z + b0, v11 = acc[i][j].w + b1;
            if (ACT == 1) {
                v00 = v00 / (1.0f + expf(-v00));
                v01 = v01 / (1.0f + expf(-v01));
                v10 = v10 / (1.0f + expf(-v10));
                v11 = v11 / (1.0f + expf(-v11));
            }
            if (HAS_ADD) {
                v00 += add[(size_t)gr0 * N + gc];
                v01 += add[(size_t)gr0 * N + gc + 1];
                v10 += add[(size_t)(gr0 + 8) * N + gc];
                v11 += add[(size_t)(gr0 + 8) * N + gc + 1];
            }
            if (SPLIT_OUT) {
                __nv_bfloat16 h00 = __float2bfloat16(v00);
                __nv_bfloat16 h01 = __float2bfloat16(v01);
                __nv_bfloat16 h10 = __float2bfloat16(v10);
                __nv_bfloat16 h11 = __float2bfloat16(v11);
                __nv_bfloat162* ch0 = reinterpret_cast<__nv_bfloat162*>(
                    Ch + (size_t)gr0 * N + gc);
                __nv_bfloat162* ch1 = reinterpret_cast<__nv_bfloat162*>(
                    Ch + (size_t)(gr0 + 8) * N + gc);
                __nv_bfloat162* cl0 = reinterpret_cast<__nv_bfloat162*>(
                    Cl + (size_t)gr0 * N + gc);
                __nv_bfloat162* cl1 = reinterpret_cast<__nv_bfloat162*>(
                    Cl + (size_t)(gr0 + 8) * N + gc);
                *ch0 = __nv_bfloat162(h00, h01);
                *ch1 = __nv_bfloat162(h10, h11);
                *cl0 = __nv_bfloat162(
                    __float2bfloat16(v00 - __bfloat162float(h00)),
                    __float2bfloat16(v01 - __bfloat162float(h01)));
                *cl1 = __nv_bfloat162(
                    __float2bfloat16(v10 - __bfloat162float(h10)),
                    __float2bfloat16(v11 - __bfloat162float(h11)));
            } else {
                *reinterpret_cast<float2*>(Cf + (size_t)gr0 * N + gc) =
                    make_float2(v00, v01);
                *reinterpret_cast<float2*>(Cf + (size_t)(gr0 + 8) * N + gc) =
                    make_float2(v10, v11);
            }
        }
    }
}

// ---------------------------------------------------------------------------
// Weight transpose + bf16 split: W[K][N] -> Th/Tl[N][K]
// ---------------------------------------------------------------------------
__global__ void transpose_split(const float* __restrict__ W,
                                __nv_bfloat16* __restrict__ Th,
                                __nv_bfloat16* __restrict__ Tl, int K, int N) {
    __shared__ float t[32][33];
    const int n0 = blockIdx.x * 32, k0 = blockIdx.y * 32;
    const int tx = threadIdx.x, ty = threadIdx.y;
#pragma unroll
    for (int dy = 0; dy < 32; dy += 8)
        t[ty + dy][tx] = W[(size_t)(k0 + ty + dy) * N + n0 + tx];
    __syncthreads();
#pragma unroll
    for (int dy = 0; dy < 32; dy += 8) {
        const int n = n0 + ty + dy, k = k0 + tx;
        float v = t[tx][ty + dy];
        __nv_bfloat16 h = __float2bfloat16(v);
        Th[(size_t)n * K + k] = h;
        Tl[(size_t)n * K + k] = __float2bfloat16(v - __bfloat162float(h));
    }
}

__global__ void split_f32(const float* __restrict__ x, __nv_bfloat16* __restrict__ h,
                          __nv_bfloat16* __restrict__ l, int n) {
    int i = blockIdx.x * 256 + threadIdx.x;
    if (i < n) {
        float v = x[i];
        __nv_bfloat16 hh = __float2bfloat16(v);
        h[i] = hh;
        l[i] = __float2bfloat16(v - __bfloat162float(hh));
    }
}

// ---------------------------------------------------------------------------
// FFT: 4096-point complex, shared memory, 256 threads
// ---------------------------------------------------------------------------
__device__ __forceinline__ float2 cmul(float2 a, float2 b) {
    return make_float2(a.x * b.x - a.y * b.y, a.x * b.y + a.y * b.x);
}

template <int SIGN>
__device__ void fft4096(float2* sm, const float2* tw) {
    const int tid = threadIdx.x;
    __syncthreads();
    for (int i = tid; i < NFFT; i += 256) {
        int r = __brev(i) >> 20;
        if (r > i) { float2 t = sm[i]; sm[i] = sm[r]; sm[r] = t; }
    }
    __syncthreads();
    for (int len = 2; len <= NFFT; len <<= 1) {
        const int half = len >> 1;
        const int step = NFFT / len;
        for (int j = tid; j < NFFT / 2; j += 256) {
            const int pos = j & (half - 1);
            const int i0  = 2 * j - pos;
            const int i1  = i0 + half;
            float2 w = tw[pos * step];
            if (SIGN > 0) w.y = -w.y;
            float2 u = sm[i0];
            float2 v = cmul(sm[i1], w);
            sm[i0] = make_float2(u.x + v.x, u.y + v.y);
            sm[i1] = make_float2(u.x - v.x, u.y - v.y);
        }
        __syncthreads();
    }
}

__device__ __forceinline__ void fill_twiddles(float2* tw) {
    for (int k = threadIdx.x; k < NFFT / 2; k += 256) {
        float s, c;
        sincosf(-6.2831853071795864769f * (float)k / (float)NFFT, &s, &c);
        tw[k] = make_float2(c, s);
    }
}

// ---------------------------------------------------------------------------
// LayerNorm (fp32 out) and LayerNorm (bf16 split out)
// ---------------------------------------------------------------------------
__global__ void layernorm_rows(const float* __restrict__ x,
                               const float* __restrict__ gvec,
                               const float* __restrict__ bvec,
                               float* __restrict__ y) {
    const int row = blockIdx.x;
    const int tid = threadIdx.x;
    const float4 v = reinterpret_cast<const float4*>(x + (size_t)row * DIM)[tid];
    float s  = v.x + v.y + v.z + v.w;
    float s2 = v.x * v.x + v.y * v.y + v.z * v.z + v.w * v.w;
    __shared__ float rs[256], rs2[256];
    rs[tid] = s; rs2[tid] = s2;
    __syncthreads();
    for (int o = 128; o > 0; o >>= 1) {
        if (tid < o) { rs[tid] += rs[tid + o]; rs2[tid] += rs2[tid + o]; }
        __syncthreads();
    }
    const float mean = rs[0] * (1.0f / DIM);
    const float var  = rs2[0] * (1.0f / DIM) - mean * mean;
    const float rstd = rsqrtf(var + LN_EPS);
    const float4 gg = reinterpret_cast<const float4*>(gvec)[tid];
    const float4 bb = reinterpret_cast<const float4*>(bvec)[tid];
    float4 o;
    o.x = (v.x - mean) * rstd * gg.x + bb.x;
    o.y = (v.y - mean) * rstd * gg.y + bb.y;
    o.z = (v.z - mean) * rstd * gg.z + bb.z;
    o.w = (v.w - mean) * rstd * gg.w + bb.w;
    reinterpret_cast<float4*>(y + (size_t)row * DIM)[tid] = o;
}

__global__ void layernorm_rows_split(const float* __restrict__ x,
                                     const float* __restrict__ gvec,
                                     const float* __restrict__ bvec,
                                     __nv_bfloat16* __restrict__ yh,
                                     __nv_bfloat16* __restrict__ yl) {
    const int row = blockIdx.x;
    const int tid = threadIdx.x;
    const float4 v = reinterpret_cast<const float4*>(x + (size_t)row * DIM)[tid];
    float s  = v.x + v.y + v.z + v.w;
    float s2 = v.x * v.x + v.y * v.y + v.z * v.z + v.w * v.w;
    __shared__ float rs[256], rs2[256];
    rs[tid] = s; rs2[tid] = s2;
    __syncthreads();
    for (int o = 128; o > 0; o >>= 1) {
        if (tid < o) { rs[tid] += rs[tid + o]; rs2[tid] += rs2[tid + o]; }
        __syncthreads();
    }
    const float mean = rs[0] * (1.0f / DIM);
    const float var  = rs2[0] * (1.0f / DIM) - mean * mean;
    const float rstd = rsqrtf(var + LN_EPS);
    const float4 gg = reinterpret_cast<const float4*>(gvec)[tid];
    const float4 bb = reinterpret_cast<const float4*>(bvec)[tid];
    float o[4];
    o[0] = (v.x - mean) * rstd * gg.x + bb.x;
    o[1] = (v.y - mean) * rstd * gg.y + bb.y;
    o[2] = (v.z - mean) * rstd * gg.z + bb.z;
    o[3] = (v.w - mean) * rstd * gg.w + bb.w;
    __nv_bfloat16 hh[4], ll[4];
#pragma unroll
    for (int j = 0; j < 4; j++) {
        hh[j] = __float2bfloat16(o[j]);
        ll[j] = __float2bfloat16(o[j] - __bfloat162float(hh[j]));
    }
    const size_t base = (size_t)row * DIM + tid * 4;
    *reinterpret_cast<ushort4*>(yh + base) = *reinterpret_cast<ushort4*>(hh);
    *reinterpret_cast<ushort4*>(yl + base) = *reinterpret_cast<ushort4*>(ll);
}

// ---------------------------------------------------------------------------
// Filter spectrum + FFT convolution
// ---------------------------------------------------------------------------
__global__ void filter_fft(const float* __restrict__ hfilt,
                           const float* __restrict__ a,
                           float2* __restrict__ wfh) {
    __shared__ float2 data[NFFT];
    __shared__ float2 tw[NFFT / 2];
    const int d   = blockIdx.x;
    const int tid = threadIdx.x;
    const float ea = expf(a[0]);
    for (int t = tid; t < LEN; t += 256) {
        float w = expf(-(float)t * ea);
        data[t] = make_float2(hfilt[(size_t)t * DIM + d] * w, 0.0f);
    }
    for (int t = LEN + tid; t < NFFT; t += 256) data[t] = make_float2(0.0f, 0.0f);
    fill_twiddles(tw);
    fft4096<-1>(data, tw);
    for (int k = tid; k < NFFT; k += 256) wfh[(size_t)d * NFFT + k] = data[k];
}

__global__ void fftconv(const float* __restrict__ lnz,
                        const float2* __restrict__ wfh,
                        const float* __restrict__ hidden,
                        float* __restrict__ znew) {
    __shared__ float2 data[NFFT];
    __shared__ float2 tw[NFFT / 2];
    const int col = blockIdx.x;
    const int b   = col >> 10;
    const int d   = col & (DIM - 1);
    const int tid = threadIdx.x;
    for (int t = tid; t < LEN; t += 256)
        data[t] = make_float2(lnz[((size_t)b * LEN + t) * DIM + d], 0.0f);
    for (int t = LEN + tid; t < NFFT; t += 256) data[t] = make_float2(0.0f, 0.0f);
    fill_twiddles(tw);
    fft4096<-1>(data, tw);
    for (int k = tid; k < NFFT; k += 256)
        data[k] = cmul(data[k], wfh[(size_t)d * NFFT + k]);
    fft4096<1>(data, tw);
    const float inv = 1.0f / (float)NFFT;
    for (int t = tid; t < LEN; t += 256)
        znew[((size_t)b * LEN + t) * DIM + d] =
            data[t].x * inv + hidden[(size_t)t * DIM + d];
}

// ---------------------------------------------------------------------------
// Launch
// ---------------------------------------------------------------------------
extern "C" void kernel_launch(void* const* d_in, const int* in_sizes, int n_in,
                              void* d_out, int out_size) {
    const float* z      = (const float*)d_in[0];
    const float* pos    = (const float*)d_in[1];
    const float* a      = (const float*)d_in[2];
    const float* hidden = (const float*)d_in[3];
    const float* ln_g   = (const float*)d_in[4];
    const float* ln_b   = (const float*)d_in[5];
    const float* wp1    = (const float*)d_in[6];
    const float* bp1    = (const float*)d_in[7];
    const float* wp2    = (const float*)d_in[8];
    const float* bp2    = (const float*)d_in[9];
    const float* w1     = (const float*)d_in[10];
    const float* b1     = (const float*)d_in[11];
    const float* w2     = (const float*)d_in[12];
    const float* b2     = (const float*)d_in[13];
    float* out = (float*)d_out;

    float *lnz, *hfilt, *znew;
    float2* wfh;
    __nv_bfloat16 *Xh, *Xl, *Hh, *Hl, *posh, *posl;
    __nv_bfloat16 *wp1t_h, *wp1t_l, *wp2t_h, *wp2t_l, *w1t_h, *w1t_l, *w2t_h, *w2t_l;
    cudaGetSymbolAddress((void**)&lnz,   g_lnz);
    cudaGetSymbolAddress((void**)&hfilt, g_hfilt);
    cudaGetSymbolAddress((void**)&wfh,   g_wfh);
    cudaGetSymbolAddress((void**)&znew,  g_znew);
    cudaGetSymbolAddress((void**)&Xh,    g_Xh);
    cudaGetSymbolAddress((void**)&Xl,    g_Xl);
    cudaGetSymbolAddress((void**)&Hh,    g_Hh);
    cudaGetSymbolAddress((void**)&Hl,    g_Hl);
    cudaGetSymbolAddress((void**)&posh,  g_posh);
    cudaGetSymbolAddress((void**)&posl,  g_posl);
    cudaGetSymbolAddress((void**)&wp1t_h, g_wp1t_h);
    cudaGetSymbolAddress((void**)&wp1t_l, g_wp1t_l);
    cudaGetSymbolAddress((void**)&wp2t_h, g_wp2t_h);
    cudaGetSymbolAddress((void**)&wp2t_l, g_wp2t_l);
    cudaGetSymbolAddress((void**)&w1t_h,  g_w1t_h);
    cudaGetSymbolAddress((void**)&w1t_l,  g_w1t_l);
    cudaGetSymbolAddress((void**)&w2t_h,  g_w2t_h);
    cudaGetSymbolAddress((void**)&w2t_l,  g_w2t_l);

    cudaFuncSetAttribute(gemm_mma<1, true,  false>,
                         cudaFuncAttributeMaxDynamicSharedMemorySize, GEMM_SMEM);
    cudaFuncSetAttribute(gemm_mma<0, false, false>,
                         cudaFuncAttributeMaxDynamicSharedMemorySize, GEMM_SMEM);
    cudaFuncSetAttribute(gemm_mma<0, false, true>,
                         cudaFuncAttributeMaxDynamicSharedMemorySize, GEMM_SMEM);

    // 0) weight prep: transpose + bf16 split
    transpose_split<<<dim3(DFF / 32, DIM / 32), dim3(32, 8)>>>(wp1, wp1t_h, wp1t_l, DIM, DFF);
    transpose_split<<<dim3(DIM / 32, DFF / 32), dim3(32, 8)>>>(wp2, wp2t_h, wp2t_l, DFF, DIM);
    transpose_split<<<dim3(DFF / 32, DIM / 32), dim3(32, 8)>>>(w1,  w1t_h,  w1t_l,  DIM, DFF);
    transpose_split<<<dim3(DIM / 32, DFF / 32), dim3(32, 8)>>>(w2,  w2t_h,  w2t_l,  DFF, DIM);
    split_f32<<<(LEN * DIM + 255) / 256, 256>>>(pos, posh, posl, LEN * DIM);

    // 1) filter FFN: H = silu(pos @ wp1 + bp1); hfilt = H @ wp2 + bp2
    gemm_mma<1, true, false><<<dim3(DFF / GBN, LEN / GBM), 256, GEMM_SMEM>>>(
        posh, posl, wp1t_h, wp1t_l, bp1, nullptr, nullptr, Hh, Hl, LEN, DFF, DIM);
    gemm_mma<0, false, false><<<dim3(DIM / GBN, LEN / GBM), 256, GEMM_SMEM>>>(
        Hh, Hl, wp2t_h, wp2t_l, bp2, nullptr, hfilt, nullptr, nullptr, LEN, DIM, DFF);

    // 2) filter spectrum
    filter_fft<<<DIM, 256>>>(hfilt, a, wfh);

    // 3) LN(z)
    layernorm_rows<<<BATCH * LEN, 256>>>(z, ln_g, ln_b, lnz);

    // 4) FFT convolution + hidden residual
    fftconv<<<BATCH * DIM, 256>>>(lnz, wfh, hidden, znew);

    // 5) LN(znew) -> split bf16
    layernorm_rows_split<<<BATCH * LEN, 256>>>(znew, ln_g, ln_b, Xh, Xl);

    // 6) main FFN + residual
    gemm_mma<1, true, false><<<dim3(DFF / GBN, (BATCH * LEN) / GBM), 256, GEMM_SMEM>>>(
        Xh, Xl, w1t_h, w1t_l, b1, nullptr, nullptr, Hh, Hl, BATCH * LEN, DFF, DIM);
    gemm_mma<0, false, true><<<dim3(DIM / GBN, (BATCH * LEN) / GBM), 256, GEMM_SMEM>>>(
        Hh, Hl, w2t_h, w2t_l, b2, znew, out, nullptr, nullptr, BATCH * LEN, DIM, DFF);
}

// round 5
// speedup vs baseline: 2.6697x; 1.3673x over previous
#include <cuda_runtime.h>
#include <cuda_bf16.h>
#include <math.h>
#include <cstdint>

// Problem constants
#define BATCH 8
#define LEN   2048
#define DIM   1024
#define DFF   4096
#define NFFT  4096
#define LN_EPS 1e-5f
#define WFS   2064        // half-spectrum row stride (2049 rounded up)

// ---------------------------------------------------------------------------
// Static device scratch (no allocation allowed)
// ---------------------------------------------------------------------------
__device__ float  g_lnz  [BATCH * LEN * DIM];      // LN(z) row-major
__device__ float  g_lnzT [BATCH * DIM * LEN];      // LN(z) transposed [b][d][t]
__device__ float  g_hfilt[LEN * DIM];              // ffn(pos) row-major
__device__ float  g_hfiltT[DIM * LEN];             // transposed [d][t]
__device__ float  g_hidT [DIM * LEN];              // hidden transposed [d][t]
__device__ float2 g_wfh  [DIM * WFS];              // filter half-spectra
__device__ float2 g_twd  [1024];                   // W_4096^k, k<1024
__device__ float  g_znewT[BATCH * DIM * LEN];      // conv out + hidden [b][d][t]
__device__ float  g_znew [BATCH * LEN * DIM];      // row-major
__device__ __nv_bfloat16 g_Xh[BATCH * LEN * DIM];
__device__ __nv_bfloat16 g_Xl[BATCH * LEN * DIM];
__device__ __nv_bfloat16 g_Hh[BATCH * LEN * DFF];
__device__ __nv_bfloat16 g_Hl[BATCH * LEN * DFF];
__device__ __nv_bfloat16 g_posh[LEN * DIM];
__device__ __nv_bfloat16 g_posl[LEN * DIM];
__device__ __nv_bfloat16 g_wp1t_h[DFF * DIM];
__device__ __nv_bfloat16 g_wp1t_l[DFF * DIM];
__device__ __nv_bfloat16 g_wp2t_h[DIM * DFF];
__device__ __nv_bfloat16 g_wp2t_l[DIM * DFF];
__device__ __nv_bfloat16 g_w1t_h[DFF * DIM];
__device__ __nv_bfloat16 g_w1t_l[DFF * DIM];
__device__ __nv_bfloat16 g_w2t_h[DIM * DFF];
__device__ __nv_bfloat16 g_w2t_l[DIM * DFF];

// ---------------------------------------------------------------------------
// PTX wrappers (baseline sm_80+ only)
// ---------------------------------------------------------------------------
__device__ __forceinline__ uint32_t smem_u32(const void* p) {
    uint32_t a;
    asm("{ .reg .u64 t; cvta.to.shared.u64 t, %1; cvt.u32.u64 %0, t; }"
        : "=r"(a) : "l"(p));
    return a;
}
__device__ __forceinline__ void cpasync16(uint32_t s, const void* g) {
    asm volatile("cp.async.cg.shared.global [%0], [%1], 16;"
                 :: "r"(s), "l"(g) : "memory");
}
__device__ __forceinline__ void cp_commit() {
    asm volatile("cp.async.commit_group;" ::: "memory");
}
template <int N>
__device__ __forceinline__ void cp_wait() {
    asm volatile("cp.async.wait_group %0;" :: "n"(N) : "memory");
}
__device__ __forceinline__ void ldm_x4(uint32_t& r0, uint32_t& r1,
                                       uint32_t& r2, uint32_t& r3, uint32_t a) {
    asm volatile("ldmatrix.sync.aligned.m8n8.x4.shared.b16 {%0,%1,%2,%3}, [%4];"
                 : "=r"(r0), "=r"(r1), "=r"(r2), "=r"(r3) : "r"(a));
}
__device__ __forceinline__ void ldm_x2(uint32_t& r0, uint32_t& r1, uint32_t a) {
    asm volatile("ldmatrix.sync.aligned.m8n8.x2.shared.b16 {%0,%1}, [%2];"
                 : "=r"(r0), "=r"(r1) : "r"(a));
}
__device__ __forceinline__ void mma_bf16(float4& d, const uint32_t* a,
                                         uint32_t b0, uint32_t b1) {
    asm volatile(
        "mma.sync.aligned.m16n8k16.row.col.f32.bf16.bf16.f32 "
        "{%0,%1,%2,%3}, {%4,%5,%6,%7}, {%8,%9}, {%0,%1,%2,%3};"
        : "+f"(d.x), "+f"(d.y), "+f"(d.z), "+f"(d.w)
        : "r"(a[0]), "r"(a[1]), "r"(a[2]), "r"(a[3]), "r"(b0), "r"(b1));
}

// ---------------------------------------------------------------------------
// HMMA GEMM (unchanged from R3, proven correct)
// ---------------------------------------------------------------------------
#define GBM 128
#define GBN 128
#define GBK 32
#define TPAD 40
#define TILE_B (128 * TPAD * 2)
#define STAGE_B (4 * TILE_B)
#define GEMM_SMEM (2 * STAGE_B)

template <int ACT, bool SPLIT_OUT, bool HAS_ADD>
__global__ __launch_bounds__(256)
void gemm_mma(const __nv_bfloat16* __restrict__ Ah, const __nv_bfloat16* __restrict__ Al,
              const __nv_bfloat16* __restrict__ Bh, const __nv_bfloat16* __restrict__ Bl,
              const float* __restrict__ bias, const float* __restrict__ add,
              float* __restrict__ Cf, __nv_bfloat16* __restrict__ Ch,
              __nv_bfloat16* __restrict__ Cl, int M, int N, int K) {
    extern __shared__ char smem[];
    const uint32_t sbase = smem_u32(smem);
    const int tid  = threadIdx.x;
    const int lane = tid & 31;
    const int wid  = tid >> 5;
    const int wm   = wid & 3;
    const int wn   = wid >> 2;
    const int bm = blockIdx.y * GBM;
    const int bn = blockIdx.x * GBN;

    const int r0 = tid >> 2;
    const int c0 = tid & 3;
    const uint32_t so0 = (uint32_t)(r0 * 80 + c0 * 16);
    const uint32_t so1 = (uint32_t)((r0 + 64) * 80 + c0 * 16);

    auto issue_loads = [&](int stage, int k0) {
        const uint32_t sb = sbase + stage * STAGE_B;
        const size_t ga0 = (size_t)(bm + r0) * K + k0 + c0 * 8;
        const size_t ga1 = (size_t)(bm + r0 + 64) * K + k0 + c0 * 8;
        const size_t gb0 = (size_t)(bn + r0) * K + k0 + c0 * 8;
        const size_t gb1 = (size_t)(bn + r0 + 64) * K + k0 + c0 * 8;
        cpasync16(sb + so0,              Ah + ga0);
        cpasync16(sb + so1,              Ah + ga1);
        cpasync16(sb + TILE_B + so0,     Al + ga0);
        cpasync16(sb + TILE_B + so1,     Al + ga1);
        cpasync16(sb + 2 * TILE_B + so0, Bh + gb0);
        cpasync16(sb + 2 * TILE_B + so1, Bh + gb1);
        cpasync16(sb + 3 * TILE_B + so0, Bl + gb0);
        cpasync16(sb + 3 * TILE_B + so1, Bl + gb1);
        cp_commit();
    };

    float4 acc[2][8];
#pragma unroll
    for (int i = 0; i < 2; i++)
#pragma unroll
        for (int j = 0; j < 8; j++) acc[i][j] = make_float4(0.f, 0.f, 0.f, 0.f);

    const int a_row = (lane & 7) + ((lane >> 3) & 1) * 8;
    const int a_kc  = ((lane >> 4) & 1) * 8;
    const int b_row = lane & 7;
    const int b_kc  = ((lane >> 3) & 1) * 8;

    const int NT = K / GBK;
    issue_loads(0, 0);

    for (int kt = 0; kt < NT; kt++) {
        if (kt + 1 < NT) issue_loads((kt + 1) & 1, (kt + 1) * GBK);
        if (kt + 1 < NT) cp_wait<1>(); else cp_wait<0>();
        __syncthreads();

        const uint32_t st = sbase + (kt & 1) * STAGE_B;
        const uint32_t As_h = st;
        const uint32_t As_l = st + TILE_B;
        const uint32_t Bs_h = st + 2 * TILE_B;
        const uint32_t Bs_l = st + 3 * TILE_B;

#pragma unroll
        for (int k16 = 0; k16 < 2; k16++) {
            uint32_t ah[2][4], al[2][4];
#pragma unroll
            for (int i = 0; i < 2; i++) {
                const uint32_t ao =
                    (uint32_t)((wm * 32 + i * 16 + a_row) * 80 +
                               (k16 * 16 + a_kc) * 2);
                ldm_x4(ah[i][0], ah[i][1], ah[i][2], ah[i][3], As_h + ao);
                ldm_x4(al[i][0], al[i][1], al[i][2], al[i][3], As_l + ao);
            }
#pragma unroll
            for (int j = 0; j < 8; j++) {
                const uint32_t bo =
                    (uint32_t)((wn * 64 + j * 8 + b_row) * 80 +
                               (k16 * 16 + b_kc) * 2);
                uint32_t bh0, bh1, bl0, bl1;
                ldm_x2(bh0, bh1, Bs_h + bo);
                ldm_x2(bl0, bl1, Bs_l + bo);
#pragma unroll
                for (int i = 0; i < 2; i++) {
                    mma_bf16(acc[i][j], ah[i], bh0, bh1);
                    mma_bf16(acc[i][j], ah[i], bl0, bl1);
                    mma_bf16(acc[i][j], al[i], bh0, bh1);
                }
            }
        }
        __syncthreads();
    }

    const int qr = lane >> 2;
    const int qc = (lane & 3) * 2;
#pragma unroll
    for (int i = 0; i < 2; i++) {
#pragma unroll
        for (int j = 0; j < 8; j++) {
            const int gr0 = bm + wm * 32 + i * 16 + qr;
            const int gc  = bn + wn * 64 + j * 8 + qc;
            const float b0 = bias[gc];
            const float b1 = bias[gc + 1];
            float v00 = acc[i][j].x + b0, v01 = acc[i][j].y + b1;
            float v10 = acc[i][j].z + b0, v11 = acc[i][j].w + b1;
            if (ACT == 1) {
                v00 = v00 / (1.0f + expf(-v00));
                v01 = v01 / (1.0f + expf(-v01));
                v10 = v10 / (1.0f + expf(-v10));
                v11 = v11 / (1.0f + expf(-v11));
            }
            if (HAS_ADD) {
                v00 += add[(size_t)gr0 * N + gc];
                v01 += add[(size_t)gr0 * N + gc + 1];
                v10 += add[(size_t)(gr0 + 8) * N + gc];
                v11 += add[(size_t)(gr0 + 8) * N + gc + 1];
            }
            if (SPLIT_OUT) {
                __nv_bfloat16 h00 = __float2bfloat16(v00);
                __nv_bfloat16 h01 = __float2bfloat16(v01);
                __nv_bfloat16 h10 = __float2bfloat16(v10);
                __nv_bfloat16 h11 = __float2bfloat16(v11);
                *reinterpret_cast<__nv_bfloat162*>(Ch + (size_t)gr0 * N + gc) =
                    __nv_bfloat162(h00, h01);
                *reinterpret_cast<__nv_bfloat162*>(Ch + (size_t)(gr0 + 8) * N + gc) =
                    __nv_bfloat162(h10, h11);
                *reinterpret_cast<__nv_bfloat162*>(Cl + (size_t)gr0 * N + gc) =
                    __nv_bfloat162(__float2bfloat16(v00 - __bfloat162float(h00)),
                                   __float2bfloat16(v01 - __bfloat162float(h01)));
                *reinterpret_cast<__nv_bfloat162*>(Cl + (size_t)(gr0 + 8) * N + gc) =
                    __nv_bfloat162(__float2bfloat16(v10 - __bfloat162float(h10)),
                                   __float2bfloat16(v11 - __bfloat162float(h11)));
            } else {
                *reinterpret_cast<float2*>(Cf + (size_t)gr0 * N + gc) =
                    make_float2(v00, v01);
                *reinterpret_cast<float2*>(Cf + (size_t)(gr0 + 8) * N + gc) =
                    make_float2(v10, v11);
            }
        }
    }
}

// ---------------------------------------------------------------------------
// Prep kernels
// ---------------------------------------------------------------------------
__global__ void transpose_split(const float* __restrict__ W,
                                __nv_bfloat16* __restrict__ Th,
                                __nv_bfloat16* __restrict__ Tl, int K, int N) {
    __shared__ float t[32][33];
    const int n0 = blockIdx.x * 32, k0 = blockIdx.y * 32;
    const int tx = threadIdx.x, ty = threadIdx.y;
#pragma unroll
    for (int dy = 0; dy < 32; dy += 8)
        t[ty + dy][tx] = W[(size_t)(k0 + ty + dy) * N + n0 + tx];
    __syncthreads();
#pragma unroll
    for (int dy = 0; dy < 32; dy += 8) {
        const int n = n0 + ty + dy, k = k0 + tx;
        float v = t[tx][ty + dy];
        __nv_bfloat16 h = __float2bfloat16(v);
        Th[(size_t)n * K + k] = h;
        Tl[(size_t)n * K + k] = __float2bfloat16(v - __bfloat162float(h));
    }
}

__global__ void split_f32(const float* __restrict__ x, __nv_bfloat16* __restrict__ h,
                          __nv_bfloat16* __restrict__ l, int n) {
    int i = blockIdx.x * 256 + threadIdx.x;
    if (i < n) {
        float v = x[i];
        __nv_bfloat16 hh = __float2bfloat16(v);
        h[i] = hh;
        l[i] = __float2bfloat16(v - __bfloat162float(hh));
    }
}

// float transpose [R][C] -> [C][R], per-batch via blockIdx.z
__global__ void transpose32f(const float* __restrict__ in, float* __restrict__ out,
                             int R, int C) {
    __shared__ float t[32][33];
    const size_t boff = (size_t)blockIdx.z * R * C;
    const float* ip = in + boff;
    float* op = out + boff;
    const int r0 = blockIdx.y * 32, c0 = blockIdx.x * 32;
    const int tx = threadIdx.x, ty = threadIdx.y;
#pragma unroll
    for (int dy = 0; dy < 32; dy += 8)
        t[ty + dy][tx] = ip[(size_t)(r0 + ty + dy) * C + c0 + tx];
    __syncthreads();
#pragma unroll
    for (int dy = 0; dy < 32; dy += 8)
        op[(size_t)(c0 + ty + dy) * R + r0 + tx] = t[tx][ty + dy];
}

__global__ void init_twd(float2* __restrict__ twd) {
    int k = blockIdx.x * 256 + threadIdx.x;
    if (k < 1024) {
        double s, c;
        sincos(-6.283185307179586476925286766559 * (double)k / 4096.0, &s, &c);
        twd[k] = make_float2((float)c, (float)s);
    }
}

// ---------------------------------------------------------------------------
// Radix-4 4096-point FFT in smem, 256 threads, padded addressing
// ---------------------------------------------------------------------------
#define PIDX(i) ((i) + ((i) >> 4))

__device__ __forceinline__ float2 cmul(float2 a, float2 b) {
    return make_float2(a.x * b.x - a.y * b.y, a.x * b.y + a.y * b.x);
}

// SIGN = -1 forward, +1 inverse (unscaled)
template <int SIGN>
__device__ void fft4096_r4(float2* sm, const float2* tw) {
    const int tid = threadIdx.x;
    __syncthreads();
    // base-4 digit-reversal permutation (involution)
    for (int i = tid; i < NFFT; i += 256) {
        int b = __brev(i) >> 20;
        int r = ((b & 0x555) << 1) | ((b >> 1) & 0x555);
        if (r > i) {
            float2 t = sm[PIDX(i)];
            sm[PIDX(i)] = sm[PIDX(r)];
            sm[PIDX(r)] = t;
        }
    }
    __syncthreads();
#pragma unroll
    for (int st = 0; st < 6; st++) {
        const int len = 4 << (2 * st);      // 4,16,...,4096
        const int q   = len >> 2;
        const int S   = NFFT / len;
#pragma unroll
        for (int u = 0; u < 4; u++) {
            const int bf = tid + u * 256;   // 0..1023
            const int g  = bf / q;
            const int j  = bf - g * q;
            const int base = g * len + j;
            float2 x0 = sm[PIDX(base)];
            float2 x1 = sm[PIDX(base + q)];
            float2 x2 = sm[PIDX(base + 2 * q)];
            float2 x3 = sm[PIDX(base + 3 * q)];
            float2 w1 = tw[j * S];
            if (SIGN > 0) w1.y = -w1.y;
            float2 w2 = cmul(w1, w1);
            float2 w3 = cmul(w1, w2);
            x1 = cmul(x1, w1);
            x2 = cmul(x2, w2);
            x3 = cmul(x3, w3);
            float2 t0 = make_float2(x0.x + x2.x, x0.y + x2.y);
            float2 t1 = make_float2(x0.x - x2.x, x0.y - x2.y);
            float2 t2 = make_float2(x1.x + x3.x, x1.y + x3.y);
            float2 t3 = make_float2(x1.x - x3.x, x1.y - x3.y);
            sm[PIDX(base)]         = make_float2(t0.x + t2.x, t0.y + t2.y);
            sm[PIDX(base + 2 * q)] = make_float2(t0.x - t2.x, t0.y - t2.y);
            if (SIGN < 0) {
                sm[PIDX(base + q)]     = make_float2(t1.x + t3.y, t1.y - t3.x);
                sm[PIDX(base + 3 * q)] = make_float2(t1.x - t3.y, t1.y + t3.x);
            } else {
                sm[PIDX(base + q)]     = make_float2(t1.x - t3.y, t1.y + t3.x);
                sm[PIDX(base + 3 * q)] = make_float2(t1.x + t3.y, t1.y - t3.x);
            }
        }
        __syncthreads();
    }
}

// ---------------------------------------------------------------------------
// Filter spectra: two channels packed per block (d0 = 2*bp, d1 = 2*bp+1)
// ---------------------------------------------------------------------------
__global__ __launch_bounds__(256)
void filter_fft_packed(const float* __restrict__ hfiltT,
                       const float* __restrict__ a,
                       float2* __restrict__ wfh,
                       const float2* __restrict__ twd) {
    __shared__ float2 sd[PIDX(NFFT)];
    __shared__ float2 tw[1024];
    const int tid = threadIdx.x;
    const int d0 = blockIdx.x * 2;
    const int d1 = d0 + 1;
    for (int i = tid; i < 1024; i += 256) tw[i] = twd[i];
    const float ea = expf(a[0]);
    for (int t = tid; t < LEN; t += 256) {
        const float w = expf(-(float)t * ea);
        sd[PIDX(t)] = make_float2(hfiltT[(size_t)d0 * LEN + t] * w,
                                  hfiltT[(size_t)d1 * LEN + t] * w);
    }
    for (int t = LEN + tid; t < NFFT; t += 256) sd[PIDX(t)] = make_float2(0.f, 0.f);
    fft4096_r4<-1>(sd, tw);
    // Hermitian split: Fa[k], Fb[k] for k in [0, 2048]
    for (int k = tid; k <= 2048; k += 256) {
        const int i2 = (NFFT - k) & (NFFT - 1);
        float2 X1 = sd[PIDX(k)];
        float2 X2 = sd[PIDX(i2)];
        float2 A = make_float2(0.5f * (X1.x + X2.x), 0.5f * (X1.y - X2.y));
        float2 B = make_float2(0.5f * (X1.y + X2.y), -0.5f * (X1.x - X2.x));
        wfh[(size_t)d0 * WFS + k] = A;
        wfh[(size_t)d1 * WFS + k] = B;
    }
}

// ---------------------------------------------------------------------------
// FFT convolution: two channels per block, coalesced I/O on transposed layout
// ---------------------------------------------------------------------------
__global__ __launch_bounds__(256)
void fftconv_packed(const float* __restrict__ lnzT,
                    const float2* __restrict__ wfh,
                    const float* __restrict__ hidT,
                    float* __restrict__ znewT,
                    const float2* __restrict__ twd) {
    __shared__ float2 sd[PIDX(NFFT)];
    __shared__ float2 tw[1024];
    const int tid = threadIdx.x;
    const int bp = blockIdx.x;              // b * 512 + dp
    const int b  = bp >> 9;
    const int d0 = (bp & 511) * 2;
    const int d1 = d0 + 1;
    for (int i = tid; i < 1024; i += 256) tw[i] = twd[i];
    const float* x0 = lnzT + ((size_t)b * DIM + d0) * LEN;
    const float* x1 = lnzT + ((size_t)b * DIM + d1) * LEN;
    for (int t = tid; t < LEN; t += 256)
        sd[PIDX(t)] = make_float2(x0[t], x1[t]);
    for (int t = LEN + tid; t < NFFT; t += 256) sd[PIDX(t)] = make_float2(0.f, 0.f);

    fft4096_r4<-1>(sd, tw);

    const float2* Fa = wfh + (size_t)d0 * WFS;
    const float2* Fb = wfh + (size_t)d1 * WFS;
    for (int k = tid; k <= 2048; k += 256) {
        const int i2 = (NFFT - k) & (NFFT - 1);
        float2 X1 = sd[PIDX(k)];
        float2 X2 = sd[PIDX(i2)];
        float2 A = make_float2(0.5f * (X1.x + X2.x), 0.5f * (X1.y - X2.y));
        float2 B = make_float2(0.5f * (X1.y + X2.y), -0.5f * (X1.x - X2.x));
        float2 Ya = cmul(A, Fa[k]);
        float2 Yb = cmul(B, Fb[k]);
        sd[PIDX(k)] = make_float2(Ya.x - Yb.y, Ya.y + Yb.x);
        if (k != 0 && k != 2048)
            sd[PIDX(i2)] = make_float2(Ya.x + Yb.y, Yb.x - Ya.y);
    }

    fft4096_r4<1>(sd, tw);

    const float inv = 1.0f / (float)NFFT;
    float* o0 = znewT + ((size_t)b * DIM + d0) * LEN;
    float* o1 = znewT + ((size_t)b * DIM + d1) * LEN;
    const float* h0 = hidT + (size_t)d0 * LEN;
    const float* h1 = hidT + (size_t)d1 * LEN;
    for (int t = tid; t < LEN; t += 256) {
        float2 v = sd[PIDX(t)];
        o0[t] = v.x * inv + h0[t];
        o1[t] = v.y * inv + h1[t];
    }
}

// ---------------------------------------------------------------------------
// LayerNorm kernels
// ---------------------------------------------------------------------------
__global__ void layernorm_rows(const float* __restrict__ x,
                               const float* __restrict__ gvec,
                               const float* __restrict__ bvec,
                               float* __restrict__ y) {
    const int row = blockIdx.x;
    const int tid = threadIdx.x;
    const float4 v = reinterpret_cast<const float4*>(x + (size_t)row * DIM)[tid];
    float s  = v.x + v.y + v.z + v.w;
    float s2 = v.x * v.x + v.y * v.y + v.z * v.z + v.w * v.w;
    __shared__ float rs[256], rs2[256];
    rs[tid] = s; rs2[tid] = s2;
    __syncthreads();
    for (int o = 128; o > 0; o >>= 1) {
        if (tid < o) { rs[tid] += rs[tid + o]; rs2[tid] += rs2[tid + o]; }
        __syncthreads();
    }
    const float mean = rs[0] * (1.0f / DIM);
    const float var  = rs2[0] * (1.0f / DIM) - mean * mean;
    const float rstd = rsqrtf(var + LN_EPS);
    const float4 gg = reinterpret_cast<const float4*>(gvec)[tid];
    const float4 bb = reinterpret_cast<const float4*>(bvec)[tid];
    float4 o;
    o.x = (v.x - mean) * rstd * gg.x + bb.x;
    o.y = (v.y - mean) * rstd * gg.y + bb.y;
    o.z = (v.z - mean) * rstd * gg.z + bb.z;
    o.w = (v.w - mean) * rstd * gg.w + bb.w;
    reinterpret_cast<float4*>(y + (size_t)row * DIM)[tid] = o;
}

__global__ void layernorm_rows_split(const float* __restrict__ x,
                                     const float* __restrict__ gvec,
                                     const float* __restrict__ bvec,
                                     __nv_bfloat16* __restrict__ yh,
                                     __nv_bfloat16* __restrict__ yl) {
    const int row = blockIdx.x;
    const int tid = threadIdx.x;
    const float4 v = reinterpret_cast<const float4*>(x + (size_t)row * DIM)[tid];
    float s  = v.x + v.y + v.z + v.w;
    float s2 = v.x * v.x + v.y * v.y + v.z * v.z + v.w * v.w;
    __shared__ float rs[256], rs2[256];
    rs[tid] = s; rs2[tid] = s2;
    __syncthreads();
    for (int o = 128; o > 0; o >>= 1) {
        if (tid < o) { rs[tid] += rs[tid + o]; rs2[tid] += rs2[tid + o]; }
        __syncthreads();
    }
    const float mean = rs[0] * (1.0f / DIM);
    const float var  = rs2[0] * (1.0f / DIM) - mean * mean;
    const float rstd = rsqrtf(var + LN_EPS);
    const float4 gg = reinterpret_cast<const float4*>(gvec)[tid];
    const float4 bb = reinterpret_cast<const float4*>(bvec)[tid];
    float o[4];
    o[0] = (v.x - mean) * rstd * gg.x + bb.x;
    o[1] = (v.y - mean) * rstd * gg.y + bb.y;
    o[2] = (v.z - mean) * rstd * gg.z + bb.z;
    o[3] = (v.w - mean) * rstd * gg.w + bb.w;
    __nv_bfloat16 hh[4], ll[4];
#pragma unroll
    for (int j = 0; j < 4; j++) {
        hh[j] = __float2bfloat16(o[j]);
        ll[j] = __float2bfloat16(o[j] - __bfloat162float(hh[j]));
    }
    const size_t base = (size_t)row * DIM + tid * 4;
    *reinterpret_cast<ushort4*>(yh + base) = *reinterpret_cast<ushort4*>(hh);
    *reinterpret_cast<ushort4*>(yl + base) = *reinterpret_cast<ushort4*>(ll);
}

// ---------------------------------------------------------------------------
// Launch
// ---------------------------------------------------------------------------
extern "C" void kernel_launch(void* const* d_in, const int* in_sizes, int n_in,
                              void* d_out, int out_size) {
    const float* z      = (const float*)d_in[0];
    const float* pos    = (const float*)d_in[1];
    const float* a      = (const float*)d_in[2];
    const float* hidden = (const float*)d_in[3];
    const float* ln_g   = (const float*)d_in[4];
    const float* ln_b   = (const float*)d_in[5];
    const float* wp1    = (const float*)d_in[6];
    const float* bp1    = (const float*)d_in[7];
    const float* wp2    = (const float*)d_in[8];
    const float* bp2    = (const float*)d_in[9];
    const float* w1     = (const float*)d_in[10];
    const float* b1     = (const float*)d_in[11];
    const float* w2     = (const float*)d_in[12];
    const float* b2     = (const float*)d_in[13];
    float* out = (float*)d_out;

    float *lnz, *lnzT, *hfilt, *hfiltT, *hidT, *znewT, *znew;
    float2 *wfh, *twd;
    __nv_bfloat16 *Xh, *Xl, *Hh, *Hl, *posh, *posl;
    __nv_bfloat16 *wp1t_h, *wp1t_l, *wp2t_h, *wp2t_l, *w1t_h, *w1t_l, *w2t_h, *w2t_l;
    cudaGetSymbolAddress((void**)&lnz,    g_lnz);
    cudaGetSymbolAddress((void**)&lnzT,   g_lnzT);
    cudaGetSymbolAddress((void**)&hfilt,  g_hfilt);
    cudaGetSymbolAddress((void**)&hfiltT, g_hfiltT);
    cudaGetSymbolAddress((void**)&hidT,   g_hidT);
    cudaGetSymbolAddress((void**)&wfh,    g_wfh);
    cudaGetSymbolAddress((void**)&twd,    g_twd);
    cudaGetSymbolAddress((void**)&znewT,  g_znewT);
    cudaGetSymbolAddress((void**)&znew,   g_znew);
    cudaGetSymbolAddress((void**)&Xh,     g_Xh);
    cudaGetSymbolAddress((void**)&Xl,     g_Xl);
    cudaGetSymbolAddress((void**)&Hh,     g_Hh);
    cudaGetSymbolAddress((void**)&Hl,     g_Hl);
    cudaGetSymbolAddress((void**)&posh,   g_posh);
    cudaGetSymbolAddress((void**)&posl,   g_posl);
    cudaGetSymbolAddress((void**)&wp1t_h, g_wp1t_h);
    cudaGetSymbolAddress((void**)&wp1t_l, g_wp1t_l);
    cudaGetSymbolAddress((void**)&wp2t_h, g_wp2t_h);
    cudaGetSymbolAddress((void**)&wp2t_l, g_wp2t_l);
    cudaGetSymbolAddress((void**)&w1t_h,  g_w1t_h);
    cudaGetSymbolAddress((void**)&w1t_l,  g_w1t_l);
    cudaGetSymbolAddress((void**)&w2t_h,  g_w2t_h);
    cudaGetSymbolAddress((void**)&w2t_l,  g_w2t_l);

    cudaFuncSetAttribute(gemm_mma<1, true,  false>,
                         cudaFuncAttributeMaxDynamicSharedMemorySize, GEMM_SMEM);
    cudaFuncSetAttribute(gemm_mma<0, false, false>,
                         cudaFuncAttributeMaxDynamicSharedMemorySize, GEMM_SMEM);
    cudaFuncSetAttribute(gemm_mma<0, false, true>,
                         cudaFuncAttributeMaxDynamicSharedMemorySize, GEMM_SMEM);

    // 0) prep: weights, pos split, twiddles, hidden transpose
    transpose_split<<<dim3(DFF / 32, DIM / 32), dim3(32, 8)>>>(wp1, wp1t_h, wp1t_l, DIM, DFF);
    transpose_split<<<dim3(DIM / 32, DFF / 32), dim3(32, 8)>>>(wp2, wp2t_h, wp2t_l, DFF, DIM);
    transpose_split<<<dim3(DFF / 32, DIM / 32), dim3(32, 8)>>>(w1,  w1t_h,  w1t_l,  DIM, DFF);
    transpose_split<<<dim3(DIM / 32, DFF / 32), dim3(32, 8)>>>(w2,  w2t_h,  w2t_l,  DFF, DIM);
    split_f32<<<(LEN * DIM + 255) / 256, 256>>>(pos, posh, posl, LEN * DIM);
    init_twd<<<4, 256>>>(twd);
    transpose32f<<<dim3(DIM / 32, LEN / 32, 1), dim3(32, 8)>>>(hidden, hidT, LEN, DIM);

    // 1) filter FFN
    gemm_mma<1, true, false><<<dim3(DFF / GBN, LEN / GBM), 256, GEMM_SMEM>>>(
        posh, posl, wp1t_h, wp1t_l, bp1, nullptr, nullptr, Hh, Hl, LEN, DFF, DIM);
    gemm_mma<0, false, false><<<dim3(DIM / GBN, LEN / GBM), 256, GEMM_SMEM>>>(
        Hh, Hl, wp2t_h, wp2t_l, bp2, nullptr, hfilt, nullptr, nullptr, LEN, DIM, DFF);
    transpose32f<<<dim3(DIM / 32, LEN / 32, 1), dim3(32, 8)>>>(hfilt, hfiltT, LEN, DIM);

    // 2) filter spectra (packed pairs)
    filter_fft_packed<<<DIM / 2, 256>>>(hfiltT, a, wfh, twd);

    // 3) LN(z) + transpose
    layernorm_rows<<<BATCH * LEN, 256>>>(z, ln_g, ln_b, lnz);
    transpose32f<<<dim3(DIM / 32, LEN / 32, BATCH), dim3(32, 8)>>>(lnz, lnzT, LEN, DIM);

    // 4) FFT convolution (packed pairs) + hidden residual -> znewT
    fftconv_packed<<<BATCH * DIM / 2, 256>>>(lnzT, wfh, hidT, znewT, twd);
    transpose32f<<<dim3(LEN / 32, DIM / 32, BATCH), dim3(32, 8)>>>(znewT, znew, DIM, LEN);

    // 5) LN(znew) -> split bf16
    layernorm_rows_split<<<BATCH * LEN, 256>>>(znew, ln_g, ln_b, Xh, Xl);

    // 6) main FFN + residual
    gemm_mma<1, true, false><<<dim3(DFF / GBN, (BATCH * LEN) / GBM), 256, GEMM_SMEM>>>(
        Xh, Xl, w1t_h, w1t_l, b1, nullptr, nullptr, Hh, Hl, BATCH * LEN, DFF, DIM);
    gemm_mma<0, false, true><<<dim3(DIM / GBN, (BATCH * LEN) / GBM), 256, GEMM_SMEM>>>(
        Hh, Hl, w2t_h, w2t_l, b2, znew, out, nullptr, nullptr, BATCH * LEN, DIM, DFF);
}